// round 4
// baseline (speedup 1.0000x reference)
#include <cuda_runtime.h>
#include <cstdint>

// ---------------------------------------------------------------------------
// kernel(i,j) = | prod_k cos((x_ik - y_jk)/2) |
//   = | Px_i * Py_j * prod_k (1 + tx_ik * ty_jk) |,  t = tan(v/2), P = prod cos(v/2)
// Stage 1 (one launch): tan tables + row/col cos-products (warp shuffle).
// Stage 2: FMA-only tiled kernel; 64x128 tile, 256 threads, 4x8 per thread.
//   Low register count (16 u64 accs) -> 4 blocks/SM -> 50% occupancy.
// ---------------------------------------------------------------------------

#define D 16
#define TM 64         // tile rows (i)
#define TN 128        // tile cols (j)
#define THREADS 256   // 16x16; each thread: 4 rows x 8 cols

__device__ float g_tx[4096 * D];
__device__ float g_ty[4096 * D];
__device__ float g_px[4096];
__device__ float g_py[4096];

typedef unsigned long long u64;

__device__ __forceinline__ u64 pack2(float lo, float hi) {
    u64 r;
    asm("mov.b64 %0, {%1, %2};" : "=l"(r) : "r"(__float_as_uint(lo)), "r"(__float_as_uint(hi)));
    return r;
}
__device__ __forceinline__ void unpack2(u64 v, float& lo, float& hi) {
    unsigned a, b;
    asm("mov.b64 {%0, %1}, %2;" : "=r"(a), "=r"(b) : "l"(v));
    lo = __uint_as_float(a);
    hi = __uint_as_float(b);
}
__device__ __forceinline__ u64 mul2(u64 a, u64 b) {
    u64 r;
    asm("mul.rn.f32x2 %0, %1, %2;" : "=l"(r) : "l"(a), "l"(b));
    return r;
}
__device__ __forceinline__ u64 fma2(u64 a, u64 b, u64 c) {
    u64 r;
    asm("fma.rn.f32x2 %0, %1, %2, %3;" : "=l"(r) : "l"(a), "l"(b), "l"(c));
    return r;
}

// ---------------------------------------------------------------------------
// Stage 1: exact sincosf; consistent clamp (same c feeds tan and product).
// 16-lane shuffle product gives per-row cos-product.
// ---------------------------------------------------------------------------
__global__ void prep_kernel(const float* __restrict__ x, const float* __restrict__ y,
                            int nx, int ny) {
    int t = blockIdx.x * blockDim.x + threadIdx.x;
    int total = nx + ny;
    bool live = t < total;
    bool inx = t < nx;
    int u = inx ? t : t - nx;
    float v = 0.0f;
    if (live) v = inx ? x[t] : y[u];
    float s, c;
    sincosf(0.5f * v, &s, &c);
    if (fabsf(c) < 1e-20f) c = copysignf(1e-20f, c);
    float tn = s / c;
    float p = c;
    p *= __shfl_xor_sync(0xffffffffu, p, 1);
    p *= __shfl_xor_sync(0xffffffffu, p, 2);
    p *= __shfl_xor_sync(0xffffffffu, p, 4);
    p *= __shfl_xor_sync(0xffffffffu, p, 8);
    if (live) {
        if (inx) g_tx[u] = tn; else g_ty[u] = tn;
        if ((u & (D - 1)) == 0) {
            int row = u >> 4;
            if (inx) g_px[row] = p; else g_py[row] = p;
        }
    }
}

// ---------------------------------------------------------------------------
// Stage 2: 64x128 tile; thread (tx,ty): rows ty*4.., cols tx*8..
// x tans duplicated (t,t) in smem -> LDS.64 broadcast;
// y tans scalar, pitch 132 floats -> aligned LDS.128 pair loads.
// ---------------------------------------------------------------------------
__global__ __launch_bounds__(THREADS, 4)
void qk_kernel(float* __restrict__ out, int n, int m) {
    __shared__ __align__(16) u64 sxt[D][TM + 2];     // 8.4 KB
    __shared__ __align__(16) float syt[D][TN + 4];   // 8.4 KB
    __shared__ __align__(16) u64 spx[TM];
    __shared__ __align__(16) float spy[TN];

    const int tid = threadIdx.x;
    const int i0 = blockIdx.y * TM;
    const int j0 = blockIdx.x * TN;

    // ---- fill shared (coalesced global reads) ----
    #pragma unroll
    for (int idx = tid; idx < TM * D; idx += THREADS) {
        int i = idx >> 4;
        int k = idx & (D - 1);
        float vx = g_tx[(i0 + i) * D + k];
        sxt[k][i] = pack2(vx, vx);
    }
    #pragma unroll
    for (int idx = tid; idx < TN * D; idx += THREADS) {
        int j = idx >> 4;
        int k = idx & (D - 1);
        syt[k][j] = g_ty[(j0 + j) * D + k];
    }
    if (tid < TM) {
        float p = g_px[i0 + tid];
        spx[tid] = pack2(p, p);
    } else if (tid < TM + TN) {
        spy[tid - TM] = g_py[j0 + tid - TM];
    }
    __syncthreads();

    const int tx = tid & 15;
    const int ty = tid >> 4;
    const int ib = ty * 4;
    const int jb = tx * 8;

    const u64 one2 = pack2(1.0f, 1.0f);
    u64 acc[4][4];
    #pragma unroll
    for (int r = 0; r < 4; ++r)
        #pragma unroll
        for (int p = 0; p < 4; ++p)
            acc[r][p] = one2;

    #pragma unroll
    for (int k = 0; k < D; ++k) {
        ulonglong2 ya = *reinterpret_cast<const ulonglong2*>(&syt[k][jb]);
        ulonglong2 yb = *reinterpret_cast<const ulonglong2*>(&syt[k][jb + 4]);
        #pragma unroll
        for (int r = 0; r < 4; ++r) {
            u64 xt = sxt[k][ib + r];   // LDS.64 broadcast
            acc[r][0] = fma2(acc[r][0], mul2(xt, ya.x), acc[r][0]);
            acc[r][1] = fma2(acc[r][1], mul2(xt, ya.y), acc[r][1]);
            acc[r][2] = fma2(acc[r][2], mul2(xt, yb.x), acc[r][2]);
            acc[r][3] = fma2(acc[r][3], mul2(xt, yb.y), acc[r][3]);
        }
    }

    // ---- epilogue: scale by Px*Py, abs, two float4 stores per row ----
    ulonglong2 pya = *reinterpret_cast<const ulonglong2*>(&spy[jb]);
    ulonglong2 pyb = *reinterpret_cast<const ulonglong2*>(&spy[jb + 4]);
    const int gj = j0 + jb;
    #pragma unroll
    for (int r = 0; r < 4; ++r) {
        u64 px2 = spx[ib + r];
        u64 v0 = mul2(mul2(acc[r][0], px2), pya.x);
        u64 v1 = mul2(mul2(acc[r][1], px2), pya.y);
        u64 v2 = mul2(mul2(acc[r][2], px2), pyb.x);
        u64 v3 = mul2(mul2(acc[r][3], px2), pyb.y);
        float a0, a1, b0, b1, c0, c1, d0, d1;
        unpack2(v0, a0, a1);
        unpack2(v1, b0, b1);
        unpack2(v2, c0, c1);
        unpack2(v3, d0, d1);
        float* row = &out[(size_t)(i0 + ib + r) * m + gj];
        *reinterpret_cast<float4*>(row) =
            make_float4(fabsf(a0), fabsf(a1), fabsf(b0), fabsf(b1));
        *reinterpret_cast<float4*>(row + 4) =
            make_float4(fabsf(c0), fabsf(c1), fabsf(d0), fabsf(d1));
    }
}

// ---------------------------------------------------------------------------
extern "C" void kernel_launch(void* const* d_in, const int* in_sizes, int n_in,
                              void* d_out, int out_size) {
    const float* x = (const float*)d_in[0];
    const float* y = (const float*)d_in[1];
    float* out = (float*)d_out;

    int nx = in_sizes[0];      // n * D
    int ny = in_sizes[1];      // m * D
    int n = nx / D;
    int m = ny / D;

    int total = nx + ny;
    prep_kernel<<<(total + 255) / 256, 256>>>(x, y, nx, ny);

    dim3 grid(m / TN, n / TM);
    qk_kernel<<<grid, THREADS>>>(out, n, m);
}

// round 7
// speedup vs baseline: 1.0454x; 1.0454x over previous
#include <cuda_runtime.h>
#include <cstdint>

// ---------------------------------------------------------------------------
// kernel(i,j) = | prod_k cos((x_ik - y_jk)/2) |
//   = | Px_i * Py_j * prod_k (1 + tx_ik * ty_jk) |,  t = tan(v/2), P = prod cos(v/2)
// Stage 1 (one launch): tan tables + row/col cos-products (warp shuffle).
// Stage 2: FMA-only tiled kernel; 64x128 tile, 256 threads, 4 rows x 8 cols
//   per thread. Columns split as {tx*4..+3} and {64+tx*4..+3} so every y
//   LDS.128 is 16B-stride across lanes -> ZERO bank conflicts (R4's tx*8
//   mapping was 4-way conflicted and saturated the smem crossbar).
// ---------------------------------------------------------------------------

#define D 16
#define TM 64         // tile rows (i)
#define TN 128        // tile cols (j)
#define THREADS 256   // 16x16; each thread: 4 rows x (4+4) cols

__device__ float g_tx[4096 * D];
__device__ float g_ty[4096 * D];
__device__ float g_px[4096];
__device__ float g_py[4096];

typedef unsigned long long u64;

__device__ __forceinline__ u64 pack2(float lo, float hi) {
    u64 r;
    asm("mov.b64 %0, {%1, %2};" : "=l"(r) : "r"(__float_as_uint(lo)), "r"(__float_as_uint(hi)));
    return r;
}
__device__ __forceinline__ void unpack2(u64 v, float& lo, float& hi) {
    unsigned a, b;
    asm("mov.b64 {%0, %1}, %2;" : "=r"(a), "=r"(b) : "l"(v));
    lo = __uint_as_float(a);
    hi = __uint_as_float(b);
}
__device__ __forceinline__ u64 mul2(u64 a, u64 b) {
    u64 r;
    asm("mul.rn.f32x2 %0, %1, %2;" : "=l"(r) : "l"(a), "l"(b));
    return r;
}
__device__ __forceinline__ u64 fma2(u64 a, u64 b, u64 c) {
    u64 r;
    asm("fma.rn.f32x2 %0, %1, %2, %3;" : "=l"(r) : "l"(a), "l"(b), "l"(c));
    return r;
}

// ---------------------------------------------------------------------------
// Stage 1: exact sincosf; consistent clamp (same c feeds tan and product).
// 16-lane shuffle product gives per-row cos-product.
// ---------------------------------------------------------------------------
__global__ void prep_kernel(const float* __restrict__ x, const float* __restrict__ y,
                            int nx, int ny) {
    int t = blockIdx.x * blockDim.x + threadIdx.x;
    int total = nx + ny;
    bool live = t < total;
    bool inx = t < nx;
    int u = inx ? t : t - nx;
    float v = 0.0f;
    if (live) v = inx ? x[t] : y[u];
    float s, c;
    sincosf(0.5f * v, &s, &c);
    if (fabsf(c) < 1e-20f) c = copysignf(1e-20f, c);
    float tn = s / c;
    float p = c;
    p *= __shfl_xor_sync(0xffffffffu, p, 1);
    p *= __shfl_xor_sync(0xffffffffu, p, 2);
    p *= __shfl_xor_sync(0xffffffffu, p, 4);
    p *= __shfl_xor_sync(0xffffffffu, p, 8);
    if (live) {
        if (inx) g_tx[u] = tn; else g_ty[u] = tn;
        if ((u & (D - 1)) == 0) {
            int row = u >> 4;
            if (inx) g_px[row] = p; else g_py[row] = p;
        }
    }
}

// ---------------------------------------------------------------------------
// Stage 2.
// ---------------------------------------------------------------------------
__global__ __launch_bounds__(THREADS, 4)
void qk_kernel(float* __restrict__ out, int n, int m) {
    __shared__ __align__(16) u64 sxt[D][TM + 2];     // x tans duplicated (t,t)
    __shared__ __align__(16) float syt[D][TN + 4];   // y tans, pitch 132 (16B mult)
    __shared__ __align__(16) u64 spx[TM];
    __shared__ __align__(16) float spy[TN];

    const int tid = threadIdx.x;
    const int i0 = blockIdx.y * TM;
    const int j0 = blockIdx.x * TN;

    // ---- fill shared (coalesced global reads) ----
    #pragma unroll
    for (int idx = tid; idx < TM * D; idx += THREADS) {
        int i = idx >> 4;
        int k = idx & (D - 1);
        float vx = g_tx[(i0 + i) * D + k];
        sxt[k][i] = pack2(vx, vx);
    }
    #pragma unroll
    for (int idx = tid; idx < TN * D; idx += THREADS) {
        int j = idx >> 4;
        int k = idx & (D - 1);
        syt[k][j] = g_ty[(j0 + j) * D + k];
    }
    if (tid < TM) {
        float p = g_px[i0 + tid];
        spx[tid] = pack2(p, p);
    } else if (tid < TM + TN) {
        spy[tid - TM] = g_py[j0 + tid - TM];
    }
    __syncthreads();

    const int tx = tid & 15;
    const int ty = tid >> 4;
    const int ib = ty * 4;
    const int ja = tx * 4;        // first col group
    const int jB = 64 + tx * 4;   // second col group (conflict-free 16B stride)

    const u64 one2 = pack2(1.0f, 1.0f);
    u64 acc[4][4];
    #pragma unroll
    for (int r = 0; r < 4; ++r)
        #pragma unroll
        for (int p = 0; p < 4; ++p)
            acc[r][p] = one2;

    #pragma unroll
    for (int k = 0; k < D; ++k) {
        ulonglong2 ya = *reinterpret_cast<const ulonglong2*>(&syt[k][ja]);  // cols ja..ja+3
        ulonglong2 yb = *reinterpret_cast<const ulonglong2*>(&syt[k][jB]);  // cols jB..jB+3
        #pragma unroll
        for (int r = 0; r < 4; ++r) {
            u64 xt = sxt[k][ib + r];   // LDS.64 broadcast
            acc[r][0] = fma2(acc[r][0], mul2(xt, ya.x), acc[r][0]);
            acc[r][1] = fma2(acc[r][1], mul2(xt, ya.y), acc[r][1]);
            acc[r][2] = fma2(acc[r][2], mul2(xt, yb.x), acc[r][2]);
            acc[r][3] = fma2(acc[r][3], mul2(xt, yb.y), acc[r][3]);
        }
    }

    // ---- epilogue: scale by Px*Py, abs, two coalesced float4 stores per row ----
    ulonglong2 pya = *reinterpret_cast<const ulonglong2*>(&spy[ja]);
    ulonglong2 pyb = *reinterpret_cast<const ulonglong2*>(&spy[jB]);
    #pragma unroll
    for (int r = 0; r < 4; ++r) {
        u64 px2 = spx[ib + r];
        u64 v0 = mul2(mul2(acc[r][0], px2), pya.x);
        u64 v1 = mul2(mul2(acc[r][1], px2), pya.y);
        u64 v2 = mul2(mul2(acc[r][2], px2), pyb.x);
        u64 v3 = mul2(mul2(acc[r][3], px2), pyb.y);
        float a0, a1, b0, b1, c0, c1, d0, d1;
        unpack2(v0, a0, a1);
        unpack2(v1, b0, b1);
        unpack2(v2, c0, c1);
        unpack2(v3, d0, d1);
        float* row = &out[(size_t)(i0 + ib + r) * m + j0];
        *reinterpret_cast<float4*>(row + ja) =
            make_float4(fabsf(a0), fabsf(a1), fabsf(b0), fabsf(b1));
        *reinterpret_cast<float4*>(row + jB) =
            make_float4(fabsf(c0), fabsf(c1), fabsf(d0), fabsf(d1));
    }
}

// ---------------------------------------------------------------------------
extern "C" void kernel_launch(void* const* d_in, const int* in_sizes, int n_in,
                              void* d_out, int out_size) {
    const float* x = (const float*)d_in[0];
    const float* y = (const float*)d_in[1];
    float* out = (float*)d_out;

    int nx = in_sizes[0];      // n * D
    int ny = in_sizes[1];      // m * D
    int n = nx / D;
    int m = ny / D;

    int total = nx + ny;
    prep_kernel<<<(total + 255) / 256, 256>>>(x, y, nx, ny);

    dim3 grid(m / TN, n / TM);
    qk_kernel<<<grid, THREADS>>>(out, n, m);
}